// round 12
// baseline (speedup 1.0000x reference)
#include <cuda_runtime.h>
#include <cuda_fp16.h>
#include <cstdint>

#define N_NODES 50000
#define N_EDGES 600000
#define LN_EPS 1e-5f

// ---------------- device-global scratch (no allocations allowed) ------------
__device__ float g_agg[N_NODES * 128];
__device__ __half g_nf[N_NODES * 128];
__device__ __half g_ag[N_NODES * 128];
// Weights per K-64 subchunk: [sc][8192 halves], B[n][k64] layout, fp16.
// Edge: sc 0-5 = We1 (K=384), 6-7 = We2. Node: sc 0-3 = Wn1, 4-5 = Wn2.
__device__ __half g_We[8 * 8192];
__device__ __half g_Wn[6 * 8192];

// ---------------- smem layout (bytes) ---------------------------------------
// X sub-tile buf: 128 rows x 128B (fp16). Two bufs. (M tile = 128)
// W sub-tile buf: 128 rows x 128B (fp16). Two bufs.
#define XB(i)     ((uint32_t)(i) * 16384u)
#define WB(i)     (32768u + (uint32_t)(i) * 16384u)
#define BIAS1_OFF 65536
#define BIAS2_OFF 66048
#define GAM_OFF   66560
#define BET_OFF   67072
#define SIDX_OFF  67584
#define RIDX_OFF  68096
#define PART_OFF  68608
#define SMEM_TOTAL 70656

// ---------------- helpers ----------------------------------------------------
__device__ __forceinline__ uint32_t smem_u32(const void* p) {
    uint32_t a;
    asm("{ .reg .u64 t; cvta.to.shared.u64 t, %1; cvt.u32.u64 %0, t; }"
        : "=r"(a) : "l"(p));
    return a;
}
__device__ __forceinline__ void ldsm4(uint32_t (&r)[4], uint32_t a) {
    asm volatile("ldmatrix.sync.aligned.m8n8.x4.shared.b16 {%0,%1,%2,%3}, [%4];"
                 : "=r"(r[0]), "=r"(r[1]), "=r"(r[2]), "=r"(r[3]) : "r"(a));
}
__device__ __forceinline__ void mma16816(float (&d)[4], const uint32_t (&a)[4],
                                         uint32_t b0, uint32_t b1) {
    asm volatile(
        "mma.sync.aligned.m16n8k16.row.col.f32.f16.f16.f32 "
        "{%0,%1,%2,%3}, {%4,%5,%6,%7}, {%8,%9}, {%0,%1,%2,%3};"
        : "+f"(d[0]), "+f"(d[1]), "+f"(d[2]), "+f"(d[3])
        : "r"(a[0]), "r"(a[1]), "r"(a[2]), "r"(a[3]), "r"(b0), "r"(b1));
}
__device__ __forceinline__ void red_add_v2(float* p, float a, float b) {
    asm volatile("red.global.add.v2.f32 [%0], {%1, %2};"
                 :: "l"(p), "f"(a), "f"(b) : "memory");
}
__device__ __forceinline__ void cp_async16(uint32_t d, const void* s) {
    asm volatile("cp.async.cg.shared.global [%0], [%1], 16;"
                 :: "r"(d), "l"(s) : "memory");
}
__device__ __forceinline__ void cp_async16z(uint32_t d, const void* s, uint32_t sz) {
    asm volatile("cp.async.cg.shared.global [%0], [%1], 16, %2;"
                 :: "r"(d), "l"(s), "r"(sz) : "memory");
}
#define CP_COMMIT() asm volatile("cp.async.commit_group;" ::: "memory")
#define CP_WAIT0()  asm volatile("cp.async.wait_group 0;" ::: "memory")

// pack two fp32 -> fp16x2
__device__ __forceinline__ uint32_t pack2h(float a, float b) {
    __half2 h = __floats2half2_rn(a, b);
    return *(uint32_t*)&h;
}

// ---------------- utility kernels (device symbols referenced in DEVICE code) -
__global__ void zero_agg_kernel() {
    int i = blockIdx.x * blockDim.x + threadIdx.x;
    ((float4*)g_agg)[i] = make_float4(0.f, 0.f, 0.f, 0.f);
}
__global__ void conv_nf_kernel(const float* __restrict__ src) {
    int i = blockIdx.x * blockDim.x + threadIdx.x;   // N_NODES*32 float4s
    float4 v = ((const float4*)src)[i];
    ((uint2*)g_nf)[i] = make_uint2(pack2h(v.x, v.y), pack2h(v.z, v.w));
}
__global__ void conv_agg_kernel() {
    int i = blockIdx.x * blockDim.x + threadIdx.x;
    float4 v = ((const float4*)g_agg)[i];
    ((uint2*)g_ag)[i] = make_uint2(pack2h(v.x, v.y), pack2h(v.z, v.w));
}
__global__ void prep_w(const float* __restrict__ We1, const float* __restrict__ We2,
                       const float* __restrict__ Wn1, const float* __restrict__ Wn2) {
    int idx = blockIdx.x * blockDim.x + threadIdx.x;
    if (idx >= 114688) return;
    __half* dst;
    float v;
    int n, kk;
    if (idx < 65536) {
        int sc = idx >> 13, rem = idx & 8191;
        n = rem >> 6; kk = rem & 63;
        v = (sc < 6) ? We1[(sc * 64 + kk) * 128 + n] : We2[((sc - 6) * 64 + kk) * 128 + n];
        dst = g_We + sc * 8192;
    } else {
        int j = idx - 65536;
        int sc = j >> 13, rem = j & 8191;
        n = rem >> 6; kk = rem & 63;
        v = (sc < 4) ? Wn1[(sc * 64 + kk) * 128 + n] : Wn2[((sc - 4) * 64 + kk) * 128 + n];
        dst = g_Wn + sc * 8192;
    }
    dst[n * 64 + kk] = __float2half_rn(v);
}

// ---------------- main fused tile kernel -------------------------------------
// 256 threads, 2 CTAs/SM, 4x2 warp grid (warp tile 32x64), M tile 128.
// 1-pass fp16 GEMM, pipelined cp.async; EDGE converts ef fp32 inline via
// LDG-prefetch (one subchunk ahead) + cvt-on-arrival + STS.64.
template <int S1, bool EDGE>
__global__ void __launch_bounds__(256, 2)
gnb_kernel(const float* __restrict__ nf, const float* __restrict__ ef,
           const int* __restrict__ snd, const int* __restrict__ rcv,
           const float* __restrict__ b1, const float* __restrict__ b2,
           const float* __restrict__ gam, const float* __restrict__ bet,
           float* __restrict__ out) {
    extern __shared__ char smem[];
    const uint32_t sb = smem_u32(smem);
    const int tid = threadIdx.x, lane = tid & 31, wid = tid >> 5;
    const int wrow = wid >> 1, wcol = wid & 1;       // 4 x 2 warp grid
    const int base = blockIdx.x * 128;
    const int total = EDGE ? N_EDGES : N_NODES;
    const int valid = min(128, total - base);

    if (tid < 128) {
        ((float*)(smem + BIAS1_OFF))[tid] = b1[tid];
        ((float*)(smem + BIAS2_OFF))[tid] = b2[tid];
        ((float*)(smem + GAM_OFF))[tid] = gam[tid];
        ((float*)(smem + BET_OFF))[tid] = bet[tid];
        if (EDGE) {
            ((int*)(smem + SIDX_OFF))[tid] = (tid < valid) ? snd[base + tid] : 0;
            ((int*)(smem + RIDX_OFF))[tid] = (tid < valid) ? rcv[base + tid] : 0;
        }
    }
    __syncthreads();

    // per-lane ldsm constants (swizzled: block b at row r lives at (b ^ (r&7))*16)
    const int aHi = lane >> 4;
    const int rA = wrow * 32 + (lane & 15);
    const int xA = rA & 7;
    const uint32_t aRow = (uint32_t)rA * 128;
    const int bHi = (lane >> 3) & 1;
    const int rB = wcol * 64 + (lane & 7) + ((lane >> 4) << 3);
    const int xB = rB & 7;
    const uint32_t bRow = (uint32_t)rB * 128;
    const int g = lane >> 2, t4 = lane & 3;

    auto issueW = [&](int sc, uint32_t woff) {
        const __half* gW = EDGE ? g_We : g_Wn;
#pragma unroll
        for (int p = 0; p < 4; ++p) {
            int m = p * 256 + tid;                  // 1024 16B chunks
            int row = m >> 3, b = m & 7;
            const __half* src = gW + sc * 8192 + row * 64 + b * 8;
            uint32_t dst = sb + woff + (uint32_t)row * 128 +
                           (uint32_t)((b ^ (row & 7)) << 4);
            cp_async16(dst, src);
        }
    };
    auto issueX = [&](int s, uint32_t xoff) {
        const int cs = s >> 1, kh = s & 1;
#pragma unroll
        for (int p = 0; p < 4; ++p) {
            int m = p * 256 + tid;                  // 1024 16B chunks (128 rows)
            int row = m >> 3, b = m & 7;
            int gr;
            const __half* sH;
            if (EDGE) {
                gr = ((const int*)(smem + (cs == 0 ? SIDX_OFF : RIDX_OFF)))[row];
                sH = g_nf;
            } else {
                gr = base + row;
                if (gr >= total) gr = total - 1;
                sH = (cs == 0) ? g_nf : g_ag;
            }
            const __half* src = sH + (size_t)gr * 128 + kh * 64 + b * 8;
            uint32_t dst = sb + xoff + (uint32_t)row * 128 +
                           (uint32_t)((b ^ (row & 7)) << 4);
            cp_async16z(dst, src, (row < valid) ? 16u : 0u);
        }
    };
    // ef fp32 prefetch (coalesced stream, one subchunk ahead), cvt on arrival
    uint32_t efreg[16];
    const int efrow = tid >> 1, efq = tid & 1;      // 2 threads per row, 32 cols
    auto ldgEF = [&](int s) {
        const int kh = s & 1;
        const float* src = ef + (size_t)(base + efrow) * 128 + kh * 64 + efq * 32;
        const bool ok = efrow < valid;
#pragma unroll
        for (int j = 0; j < 8; ++j) {
            float4 v = ok ? ((const float4*)src)[j] : make_float4(0.f, 0.f, 0.f, 0.f);
            efreg[j * 2]     = pack2h(v.x, v.y);
            efreg[j * 2 + 1] = pack2h(v.z, v.w);
        }
    };
    auto stsEF = [&](uint32_t xoff) {
        char* tb = smem + xoff;
#pragma unroll
        for (int j = 0; j < 8; ++j) {
            const int kk = efq * 32 + j * 4;
            const int blk = kk >> 3;
            const uint32_t o = (uint32_t)efrow * 128 +
                               (uint32_t)((blk ^ (efrow & 7)) << 4) + (kk & 7) * 2;
            *(uint2*)(tb + o) = make_uint2(efreg[j * 2], efreg[j * 2 + 1]);
        }
    };
    // 64-wide-K subchunk: acc += X*W, 1-pass fp16, warp tile 32x64.
    auto compute_sub = [&](float (&acc)[2][8][4], uint32_t xbase, uint32_t wbase) {
#pragma unroll
        for (int ks = 0; ks < 4; ++ks) {
            const uint32_t oA = aRow + (uint32_t)((((2 * ks + aHi) ^ xA)) << 4);
            const uint32_t oB = bRow + (uint32_t)((((2 * ks + bHi) ^ xB)) << 4);
            uint32_t ah[2][4], bh[4][4];
            ldsm4(ah[0], xbase + oA);
            ldsm4(ah[1], xbase + oA + 2048);
#pragma unroll
            for (int nj = 0; nj < 4; ++nj)
                ldsm4(bh[nj], wbase + oB + nj * 2048);
#pragma unroll
            for (int mi = 0; mi < 2; ++mi)
#pragma unroll
                for (int nj = 0; nj < 4; ++nj) {
                    mma16816(acc[mi][2 * nj],     ah[mi], bh[nj][0], bh[nj][1]);
                    mma16816(acc[mi][2 * nj + 1], ah[mi], bh[nj][2], bh[nj][3]);
                }
        }
    };

    float acc[2][8][4];
#pragma unroll
    for (int mi = 0; mi < 2; ++mi)
#pragma unroll
        for (int ni = 0; ni < 8; ++ni)
#pragma unroll
            for (int r = 0; r < 4; ++r) acc[mi][ni][r] = 0.f;

    // ---------------- GEMM1: pipelined over S1 subchunks --------------------
    issueX(0, XB(0));
    issueW(0, WB(0));
    CP_COMMIT();
#pragma unroll
    for (int s = 0; s < S1; ++s) {
        CP_WAIT0();
        __syncthreads();
        const bool curEF = EDGE && (s >> 1) == 2;
        if (curEF) {
            stsEF(XB(s & 1));
            __syncthreads();
        }
        if (s + 1 < S1) {
            const bool nxtEF = EDGE && ((s + 1) >> 1) == 2;
            if (nxtEF) ldgEF(s + 1);
            else       issueX(s + 1, XB((s + 1) & 1));
            issueW(s + 1, WB((s + 1) & 1));
            CP_COMMIT();
        }
        compute_sub(acc, sb + XB(s & 1), sb + WB(s & 1));
        __syncthreads();
    }

    // ---------------- W2 prefetch (safe: all GEMM1 compute done) ------------
    issueW(S1, WB(0));
    issueW(S1 + 1, WB(1));
    CP_COMMIT();

    // ---------------- epilogue 1: h = relu(y1+b1) -> H tiles ----------------
    {
        const float* s_b1 = (const float*)(smem + BIAS1_OFF);
#pragma unroll
        for (int mi = 0; mi < 2; ++mi) {
            const int r0 = wrow * 32 + mi * 16 + g, r1 = r0 + 8;
#pragma unroll
            for (int ni = 0; ni < 8; ++ni) {
                const int col = wcol * 64 + ni * 8 + t4 * 2;
                const float ba = s_b1[col], bb = s_b1[col + 1];
                float v0 = fmaxf(acc[mi][ni][0] + ba, 0.f);
                float v1 = fmaxf(acc[mi][ni][1] + bb, 0.f);
                float v2 = fmaxf(acc[mi][ni][2] + ba, 0.f);
                float v3 = fmaxf(acc[mi][ni][3] + bb, 0.f);
                uint32_t h0 = pack2h(v0, v1);
                uint32_t h1 = pack2h(v2, v3);
                const int sub = col >> 6, kk = col & 63;
                const int bblk = kk >> 3, w2 = (kk & 7) * 2;
                char* tb = smem + sub * 16384;    // H subchunk -> XB(sub)
                char* d0 = tb + r0 * 128 + (((bblk ^ (r0 & 7))) << 4) + w2;
                char* d1 = tb + r1 * 128 + (((bblk ^ (r1 & 7))) << 4) + w2;
                *(uint32_t*)d0 = h0;
                *(uint32_t*)d1 = h1;
            }
        }
        // reset accumulators for GEMM2 (register reuse)
#pragma unroll
        for (int mi = 0; mi < 2; ++mi)
#pragma unroll
            for (int ni = 0; ni < 8; ++ni)
#pragma unroll
                for (int r = 0; r < 4; ++r) acc[mi][ni][r] = 0.f;
    }
    CP_WAIT0();
    __syncthreads();

    // ---------------- GEMM2: 2 subchunks (H in XB0/XB1, W2 in WB0/WB1) ------
    compute_sub(acc, sb + XB(0), sb + WB(0));
    compute_sub(acc, sb + XB(1), sb + WB(1));

    // ---------------- epilogue 2: LayerNorm + residual + scatter ------------
    {
        const float* s_b2 = (const float*)(smem + BIAS2_OFF);
        float s[2][2] = {{0.f, 0.f}, {0.f, 0.f}};
        float ss[2][2] = {{0.f, 0.f}, {0.f, 0.f}};
#pragma unroll
        for (int mi = 0; mi < 2; ++mi)
#pragma unroll
            for (int ni = 0; ni < 8; ++ni) {
                const int col = wcol * 64 + ni * 8 + t4 * 2;
                const float ba = s_b2[col], bb = s_b2[col + 1];
                float y0 = acc[mi][ni][0] + ba, y1 = acc[mi][ni][1] + bb;
                float y2 = acc[mi][ni][2] + ba, y3 = acc[mi][ni][3] + bb;
                acc[mi][ni][0] = y0; acc[mi][ni][1] = y1;
                acc[mi][ni][2] = y2; acc[mi][ni][3] = y3;
                s[mi][0] += y0 + y1; ss[mi][0] += y0 * y0 + y1 * y1;
                s[mi][1] += y2 + y3; ss[mi][1] += y2 * y2 + y3 * y3;
            }
#pragma unroll
        for (int off = 1; off <= 2; off <<= 1)
#pragma unroll
            for (int mi = 0; mi < 2; ++mi)
#pragma unroll
                for (int h = 0; h < 2; ++h) {
                    s[mi][h] += __shfl_xor_sync(0xffffffffu, s[mi][h], off);
                    ss[mi][h] += __shfl_xor_sync(0xffffffffu, ss[mi][h], off);
                }
        float2* part = (float2*)(smem + PART_OFF);
        if (t4 == 0)
#pragma unroll
            for (int mi = 0; mi < 2; ++mi)
#pragma unroll
                for (int h = 0; h < 2; ++h) {
                    const int row = wrow * 32 + mi * 16 + g + h * 8;
                    part[row * 2 + wcol] = make_float2(s[mi][h], ss[mi][h]);
                }
        __syncthreads();

        const float* s_g = (const float*)(smem + GAM_OFF);
        const float* s_bb = (const float*)(smem + BET_OFF);
#pragma unroll
        for (int mi = 0; mi < 2; ++mi)
#pragma unroll
            for (int h = 0; h < 2; ++h) {
                const int row = wrow * 32 + mi * 16 + g + h * 8;
                if (row >= valid) continue;
                float2 p0 = part[row * 2], p1 = part[row * 2 + 1];
                const float mu = (p0.x + p1.x) * (1.f / 128.f);
                const float var = (p0.y + p1.y) * (1.f / 128.f) - mu * mu;
                const float inv = rsqrtf(var + LN_EPS);
                const size_t gro = (size_t)(base + row) * 128;
                const float* res = (EDGE ? ef : nf) + gro;
                float* op = out + gro;
                float* ap = nullptr;
                if (EDGE) {
                    const int rv = ((const int*)(smem + RIDX_OFF))[row];
                    ap = g_agg + (size_t)rv * 128;
                }
#pragma unroll
                for (int ni = 0; ni < 8; ++ni) {
                    const int col = wcol * 64 + ni * 8 + t4 * 2;
                    const float y0 = acc[mi][ni][h * 2];
                    const float y1 = acc[mi][ni][h * 2 + 1];
                    const float m0 = (y0 - mu) * inv * s_g[col] + s_bb[col];
                    const float m1 = (y1 - mu) * inv * s_g[col + 1] + s_bb[col + 1];
                    if (EDGE) red_add_v2(ap + col, m0, m1);
                    float2 r2 = *(const float2*)(res + col);
                    *(float2*)(op + col) = make_float2(m0 + r2.x, m1 + r2.y);
                }
            }
    }
}

// ---------------------------------------------------------------------------
extern "C" void kernel_launch(void* const* d_in, const int* in_sizes, int n_in,
                              void* d_out, int out_size) {
    const float* nf  = (const float*)d_in[0];
    const float* ef  = (const float*)d_in[1];
    const int*   snd = (const int*)d_in[2];
    const int*   rcv = (const int*)d_in[3];
    const float* We1 = (const float*)d_in[4];
    const float* be1 = (const float*)d_in[5];
    const float* We2 = (const float*)d_in[6];
    const float* be2 = (const float*)d_in[7];
    const float* ge  = (const float*)d_in[8];
    const float* bbe = (const float*)d_in[9];
    const float* Wn1 = (const float*)d_in[10];
    const float* bn1 = (const float*)d_in[11];
    const float* Wn2 = (const float*)d_in[12];
    const float* bn2 = (const float*)d_in[13];
    const float* gn  = (const float*)d_in[14];
    const float* bbn = (const float*)d_in[15];

    float* out_nodes = (float*)d_out;
    float* out_edges = out_nodes + (size_t)N_NODES * 128;

    cudaFuncSetAttribute(gnb_kernel<6, true>,
                         cudaFuncAttributeMaxDynamicSharedMemorySize, SMEM_TOTAL);
    cudaFuncSetAttribute(gnb_kernel<4, false>,
                         cudaFuncAttributeMaxDynamicSharedMemorySize, SMEM_TOTAL);

    prep_w<<<448, 256>>>(We1, We2, Wn1, Wn2);
    conv_nf_kernel<<<6250, 256>>>(nf);       // 50000*32 float4s
    zero_agg_kernel<<<6250, 256>>>();

    gnb_kernel<6, true><<<(N_EDGES + 127) / 128, 256, SMEM_TOTAL>>>(
        nf, ef, snd, rcv, be1, be2, ge, bbe, out_edges);

    conv_agg_kernel<<<6250, 256>>>();

    gnb_kernel<4, false><<<(N_NODES + 127) / 128, 256, SMEM_TOTAL>>>(
        nf, nullptr, nullptr, nullptr, bn1, bn2, gn, bbn, out_nodes);
}

// round 13
// speedup vs baseline: 1.0529x; 1.0529x over previous
#include <cuda_runtime.h>
#include <cuda_fp16.h>
#include <cstdint>

#define N_NODES 50000
#define N_EDGES 600000
#define LN_EPS 1e-5f

// ---------------- device-global scratch (no allocations allowed) ------------
__device__ float g_agg[N_NODES * 128];
__device__ __half g_nf[N_NODES * 128];
__device__ __half g_ag[N_NODES * 128];
// Weights per K-64 subchunk, PRE-SWIZZLED (ldmatrix XOR layout), 16KB each.
// Edge: sc 0-5 = We1 (K=384), 6-7 = We2. Node: sc 0-3 = Wn1, 4-5 = Wn2.
__device__ __align__(16) __half g_We[8 * 8192];
__device__ __align__(16) __half g_Wn[6 * 8192];

// ---------------- smem layout (bytes) ---------------------------------------
// X sub-tile buf: 64 rows x 128B (fp16). Two bufs.
// W sub-tile buf: 128 rows x 128B (fp16). Two bufs (bulk-DMA filled).
#define XB(i)     ((uint32_t)(i) * 8192u)
#define WB(i)     (16384u + (uint32_t)(i) * 16384u)
#define BIAS1_OFF 49152
#define BIAS2_OFF 49664
#define GAM_OFF   50176
#define BET_OFF   50688
#define SIDX_OFF  51200
#define RIDX_OFF  51456
#define PART_OFF  51712
#define MBAR_OFF  53760          // 2 x 8B mbarriers for W bulk copies
#define SMEM_TOTAL 53824

// ---------------- helpers ----------------------------------------------------
__device__ __forceinline__ uint32_t smem_u32(const void* p) {
    uint32_t a;
    asm("{ .reg .u64 t; cvta.to.shared.u64 t, %1; cvt.u32.u64 %0, t; }"
        : "=r"(a) : "l"(p));
    return a;
}
__device__ __forceinline__ void ldsm4(uint32_t (&r)[4], uint32_t a) {
    asm volatile("ldmatrix.sync.aligned.m8n8.x4.shared.b16 {%0,%1,%2,%3}, [%4];"
                 : "=r"(r[0]), "=r"(r[1]), "=r"(r[2]), "=r"(r[3]) : "r"(a));
}
__device__ __forceinline__ void mma16816(float (&d)[4], const uint32_t (&a)[4],
                                         uint32_t b0, uint32_t b1) {
    asm volatile(
        "mma.sync.aligned.m16n8k16.row.col.f32.f16.f16.f32 "
        "{%0,%1,%2,%3}, {%4,%5,%6,%7}, {%8,%9}, {%0,%1,%2,%3};"
        : "+f"(d[0]), "+f"(d[1]), "+f"(d[2]), "+f"(d[3])
        : "r"(a[0]), "r"(a[1]), "r"(a[2]), "r"(a[3]), "r"(b0), "r"(b1));
}
__device__ __forceinline__ void red_add_v2(float* p, float a, float b) {
    asm volatile("red.global.add.v2.f32 [%0], {%1, %2};"
                 :: "l"(p), "f"(a), "f"(b) : "memory");
}
__device__ __forceinline__ void cp_async16(uint32_t d, const void* s) {
    asm volatile("cp.async.cg.shared.global [%0], [%1], 16;"
                 :: "r"(d), "l"(s) : "memory");
}
__device__ __forceinline__ void cp_async16z(uint32_t d, const void* s, uint32_t sz) {
    asm volatile("cp.async.cg.shared.global [%0], [%1], 16, %2;"
                 :: "r"(d), "l"(s), "r"(sz) : "memory");
}
#define CP_COMMIT() asm volatile("cp.async.commit_group;" ::: "memory")
#define CP_WAIT0()  asm volatile("cp.async.wait_group 0;" ::: "memory")

__device__ __forceinline__ void mbar_init(uint32_t a, uint32_t c) {
    asm volatile("mbarrier.init.shared.b64 [%0], %1;" :: "r"(a), "r"(c) : "memory");
}
__device__ __forceinline__ void mbar_expect(uint32_t a, uint32_t bytes) {
    asm volatile("mbarrier.arrive.expect_tx.shared.b64 _, [%0], %1;"
                 :: "r"(a), "r"(bytes) : "memory");
}
__device__ __forceinline__ void bulk_g2s(uint32_t dst, const void* src,
                                         uint32_t bytes, uint32_t mbar) {
    asm volatile(
        "cp.async.bulk.shared::cta.global.mbarrier::complete_tx::bytes "
        "[%0], [%1], %2, [%3];"
        :: "r"(dst), "l"(src), "r"(bytes), "r"(mbar) : "memory");
}
__device__ __forceinline__ void mbar_wait(uint32_t addr, uint32_t parity) {
    uint32_t done;
    do {
        asm volatile(
            "{\n\t.reg .pred P;\n\t"
            "mbarrier.try_wait.parity.acquire.cta.shared::cta.b64 P, [%1], %2, 0x989680;\n\t"
            "selp.b32 %0, 1, 0, P;\n\t}"
            : "=r"(done) : "r"(addr), "r"(parity) : "memory");
    } while (!done);
}

// pack two fp32 -> fp16x2
__device__ __forceinline__ uint32_t pack2h(float a, float b) {
    __half2 h = __floats2half2_rn(a, b);
    return *(uint32_t*)&h;
}

// ---------------- utility kernels (device symbols referenced in DEVICE code) -
__global__ void zero_agg_kernel() {
    int i = blockIdx.x * blockDim.x + threadIdx.x;
    ((float4*)g_agg)[i] = make_float4(0.f, 0.f, 0.f, 0.f);
}
__global__ void conv_nf_kernel(const float* __restrict__ src) {
    int i = blockIdx.x * blockDim.x + threadIdx.x;   // N_NODES*32 float4s
    float4 v = ((const float4*)src)[i];
    ((uint2*)g_nf)[i] = make_uint2(pack2h(v.x, v.y), pack2h(v.z, v.w));
}
__global__ void conv_agg_kernel() {
    int i = blockIdx.x * blockDim.x + threadIdx.x;
    float4 v = ((const float4*)g_agg)[i];
    ((uint2*)g_ag)[i] = make_uint2(pack2h(v.x, v.y), pack2h(v.z, v.w));
}
// Write W pre-swizzled: element (n, kk) -> byte n*128 + ((kk>>3 ^ (n&7))<<4) + (kk&7)*2
__global__ void prep_w(const float* __restrict__ We1, const float* __restrict__ We2,
                       const float* __restrict__ Wn1, const float* __restrict__ Wn2) {
    int idx = blockIdx.x * blockDim.x + threadIdx.x;
    if (idx >= 114688) return;
    char* dst;
    float v;
    int n, kk;
    if (idx < 65536) {
        int sc = idx >> 13, rem = idx & 8191;
        n = rem >> 6; kk = rem & 63;
        v = (sc < 6) ? We1[(sc * 64 + kk) * 128 + n] : We2[((sc - 6) * 64 + kk) * 128 + n];
        dst = (char*)(g_We + sc * 8192);
    } else {
        int j = idx - 65536;
        int sc = j >> 13, rem = j & 8191;
        n = rem >> 6; kk = rem & 63;
        v = (sc < 4) ? Wn1[(sc * 64 + kk) * 128 + n] : Wn2[((sc - 4) * 64 + kk) * 128 + n];
        dst = (char*)(g_Wn + sc * 8192);
    }
    uint32_t off = (uint32_t)n * 128 + (uint32_t)(((kk >> 3) ^ (n & 7)) << 4) +
                   (uint32_t)(kk & 7) * 2;
    *(__half*)(dst + off) = __float2half_rn(v);
}

// ---------------- main fused tile kernel -------------------------------------
// 256 threads, 3 CTAs/SM, 2x4 warp grid (warp tile 32x32), M tile 64.
// 1-pass fp16 GEMM. W via cp.async.bulk (TMA-engine DMA, pre-swizzled global).
// X via cp.async; EDGE converts ef inline (LDG prefetch + cvt + STS.64).
template <int S1, bool EDGE>
__global__ void __launch_bounds__(256, 3)
gnb_kernel(const float* __restrict__ nf, const float* __restrict__ ef,
           const int* __restrict__ snd, const int* __restrict__ rcv,
           const float* __restrict__ b1, const float* __restrict__ b2,
           const float* __restrict__ gam, const float* __restrict__ bet,
           float* __restrict__ out) {
    extern __shared__ char smem[];
    const uint32_t sb = smem_u32(smem);
    const int tid = threadIdx.x, lane = tid & 31, wid = tid >> 5;
    const int wrow = wid >> 2, wcol = wid & 3;
    const int base = blockIdx.x * 64;
    const int total = EDGE ? N_EDGES : N_NODES;
    const int valid = min(64, total - base);

    if (tid == 0) {
        mbar_init(sb + MBAR_OFF, 1);
        mbar_init(sb + MBAR_OFF + 8, 1);
    }
    if (tid < 128) {
        ((float*)(smem + BIAS1_OFF))[tid] = b1[tid];
        ((float*)(smem + BIAS2_OFF))[tid] = b2[tid];
        ((float*)(smem + GAM_OFF))[tid] = gam[tid];
        ((float*)(smem + BET_OFF))[tid] = bet[tid];
    }
    if (EDGE && tid < 64) {
        ((int*)(smem + SIDX_OFF))[tid] = (tid < valid) ? snd[base + tid] : 0;
        ((int*)(smem + RIDX_OFF))[tid] = (tid < valid) ? rcv[base + tid] : 0;
    }
    __syncthreads();

    // per-lane ldsm constants (swizzled: block b at row r lives at (b ^ (r&7))*16)
    const int aHi = lane >> 4;
    const int rA = wrow * 32 + (lane & 15);
    const int xA = rA & 7;
    const uint32_t aRow = (uint32_t)rA * 128;
    const int bHi = (lane >> 3) & 1;
    const int rB = wcol * 32 + (lane & 7) + ((lane >> 4) << 3);
    const int xB = rB & 7;
    const uint32_t bRow = (uint32_t)rB * 128;
    const int g = lane >> 2, t4 = lane & 3;

    // bulk W load: one DMA per 16KB subchunk (pre-swizzled in global)
    auto issueW = [&](int sc, int buf) {
        if (tid == 0) {
            const __half* gW = EDGE ? g_We : g_Wn;
            mbar_expect(sb + MBAR_OFF + 8 * buf, 16384u);
            bulk_g2s(sb + WB(buf), gW + sc * 8192, 16384u, sb + MBAR_OFF + 8 * buf);
        }
    };
    auto issueX = [&](int s, uint32_t xoff) {
        const int cs = s >> 1, kh = s & 1;
#pragma unroll
        for (int p = 0; p < 2; ++p) {
            int m = p * 256 + tid;                  // 512 16B chunks
            int row = m >> 3, b = m & 7;
            int gr;
            const __half* sH;
            if (EDGE) {
                gr = ((const int*)(smem + (cs == 0 ? SIDX_OFF : RIDX_OFF)))[row];
                sH = g_nf;
            } else {
                gr = base + row;
                if (gr >= total) gr = total - 1;
                sH = (cs == 0) ? g_nf : g_ag;
            }
            const __half* src = sH + (size_t)gr * 128 + kh * 64 + b * 8;
            uint32_t dst = sb + xoff + (uint32_t)row * 128 +
                           (uint32_t)((b ^ (row & 7)) << 4);
            cp_async16z(dst, src, (row < valid) ? 16u : 0u);
        }
    };
    // ef fp32 prefetch (coalesced stream, one subchunk ahead), cvt on arrival
    uint32_t efreg[8];
    const int efrow = tid >> 2, efq = tid & 3;
    auto ldgEF = [&](int s) {
        const int kh = s & 1;
        const float* src = ef + (size_t)(base + efrow) * 128 + kh * 64 + efq * 16;
#pragma unroll
        for (int j = 0; j < 4; ++j) {
            float4 v = ((const float4*)src)[j];
            efreg[j * 2]     = pack2h(v.x, v.y);
            efreg[j * 2 + 1] = pack2h(v.z, v.w);
        }
    };
    auto stsEF = [&](uint32_t xoff) {
        char* tb = smem + xoff;
#pragma unroll
        for (int j = 0; j < 2; ++j) {
            const int kk = efq * 16 + j * 8;
            const int blk = kk >> 3;
            const uint32_t o = (uint32_t)efrow * 128 +
                               (uint32_t)((blk ^ (efrow & 7)) << 4);
            *(uint4*)(tb + o) = make_uint4(efreg[j * 4], efreg[j * 4 + 1],
                                           efreg[j * 4 + 2], efreg[j * 4 + 3]);
        }
    };
    // 64-wide-K subchunk: acc += X*W, 1-pass fp16.
    auto compute_sub = [&](float (&acc)[2][4][4], uint32_t xbase, uint32_t wbase) {
#pragma unroll
        for (int ks = 0; ks < 4; ++ks) {
            const uint32_t oA = aRow + (uint32_t)((((2 * ks + aHi) ^ xA)) << 4);
            const uint32_t oB = bRow + (uint32_t)((((2 * ks + bHi) ^ xB)) << 4);
            uint32_t ah[2][4], bh[2][4];
            ldsm4(ah[0], xbase + oA);
            ldsm4(ah[1], xbase + oA + 2048);
            ldsm4(bh[0], wbase + oB);
            ldsm4(bh[1], wbase + oB + 2048);
#pragma unroll
            for (int mi = 0; mi < 2; ++mi)
#pragma unroll
                for (int nj = 0; nj < 2; ++nj) {
                    mma16816(acc[mi][2 * nj],     ah[mi], bh[nj][0], bh[nj][1]);
                    mma16816(acc[mi][2 * nj + 1], ah[mi], bh[nj][2], bh[nj][3]);
                }
        }
    };

    float acc[2][4][4];
#pragma unroll
    for (int mi = 0; mi < 2; ++mi)
#pragma unroll
        for (int ni = 0; ni < 4; ++ni)
#pragma unroll
            for (int r = 0; r < 4; ++r) acc[mi][ni][r] = 0.f;

    // ---------------- GEMM1: pipelined over S1 subchunks --------------------
    issueX(0, XB(0));
    CP_COMMIT();
    issueW(0, 0);
#pragma unroll
    for (int s = 0; s < S1; ++s) {
        CP_WAIT0();                              // X buf (s&1) ready
        mbar_wait(sb + MBAR_OFF + 8 * (s & 1), (s >> 1) & 1);   // W buf ready
        __syncthreads();
        const bool curEF = EDGE && (s >> 1) == 2;
        if (curEF) {
            stsEF(XB(s & 1));
            __syncthreads();
        }
        if (s + 1 < S1) {
            const bool nxtEF = EDGE && ((s + 1) >> 1) == 2;
            if (nxtEF) ldgEF(s + 1);
            else       issueX(s + 1, XB((s + 1) & 1));
            CP_COMMIT();
            issueW(s + 1, (s + 1) & 1);
        }
        compute_sub(acc, sb + XB(s & 1), sb + WB(s & 1));
        __syncthreads();
    }

    // ---------------- W2 prefetch (safe: all GEMM1 compute done) ------------
    issueW(S1, 0);
    issueW(S1 + 1, 1);

    // ---------------- epilogue 1: h = relu(y1+b1) -> H tiles ----------------
    {
        const float* s_b1 = (const float*)(smem + BIAS1_OFF);
#pragma unroll
        for (int mi = 0; mi < 2; ++mi) {
            const int r0 = wrow * 32 + mi * 16 + g, r1 = r0 + 8;
#pragma unroll
            for (int ni = 0; ni < 4; ++ni) {
                const int col = wcol * 32 + ni * 8 + t4 * 2;
                const float ba = s_b1[col], bb = s_b1[col + 1];
                float v0 = fmaxf(acc[mi][ni][0] + ba, 0.f);
                float v1 = fmaxf(acc[mi][ni][1] + bb, 0.f);
                float v2 = fmaxf(acc[mi][ni][2] + ba, 0.f);
                float v3 = fmaxf(acc[mi][ni][3] + bb, 0.f);
                uint32_t h0 = pack2h(v0, v1);
                uint32_t h1 = pack2h(v2, v3);
                const int sub = col >> 6, kk = col & 63;
                const int bblk = kk >> 3, w2 = (kk & 7) * 2;
                char* tb = smem + sub * 8192;     // H subchunk -> XB(sub)
                char* d0 = tb + r0 * 128 + (((bblk ^ (r0 & 7))) << 4) + w2;
                char* d1 = tb + r1 * 128 + (((bblk ^ (r1 & 7))) << 4) + w2;
                *(uint32_t*)d0 = h0;
                *(uint32_t*)d1 = h1;
            }
        }
        // reset accumulators for GEMM2 (register reuse)
#pragma unroll
        for (int mi = 0; mi < 2; ++mi)
#pragma unroll
            for (int ni = 0; ni < 4; ++ni)
#pragma unroll
                for (int r = 0; r < 4; ++r) acc[mi][ni][r] = 0.f;
    }
    mbar_wait(sb + MBAR_OFF, (S1 / 2) & 1);
    mbar_wait(sb + MBAR_OFF + 8, (S1 / 2) & 1);
    __syncthreads();

    // ---------------- GEMM2: 2 subchunks (H in XB0/XB1, W2 in WB0/WB1) ------
    compute_sub(acc, sb + XB(0), sb + WB(0));
    compute_sub(acc, sb + XB(1), sb + WB(1));

    // ---------------- epilogue 2: LayerNorm + residual + scatter ------------
    {
        const float* s_b2 = (const float*)(smem + BIAS2_OFF);
        float s[2][2] = {{0.f, 0.f}, {0.f, 0.f}};
        float ss[2][2] = {{0.f, 0.f}, {0.f, 0.f}};
#pragma unroll
        for (int mi = 0; mi < 2; ++mi)
#pragma unroll
            for (int ni = 0; ni < 4; ++ni) {
                const int col = wcol * 32 + ni * 8 + t4 * 2;
                const float ba = s_b2[col], bb = s_b2[col + 1];
                float y0 = acc[mi][ni][0] + ba, y1 = acc[mi][ni][1] + bb;
                float y2 = acc[mi][ni][2] + ba, y3 = acc[mi][ni][3] + bb;
                acc[mi][ni][0] = y0; acc[mi][ni][1] = y1;
                acc[mi][ni][2] = y2; acc[mi][ni][3] = y3;
                s[mi][0] += y0 + y1; ss[mi][0] += y0 * y0 + y1 * y1;
                s[mi][1] += y2 + y3; ss[mi][1] += y2 * y2 + y3 * y3;
            }
#pragma unroll
        for (int off = 1; off <= 2; off <<= 1)
#pragma unroll
            for (int mi = 0; mi < 2; ++mi)
#pragma unroll
                for (int h = 0; h < 2; ++h) {
                    s[mi][h] += __shfl_xor_sync(0xffffffffu, s[mi][h], off);
                    ss[mi][h] += __shfl_xor_sync(0xffffffffu, ss[mi][h], off);
                }
        float2* part = (float2*)(smem + PART_OFF);
        if (t4 == 0)
#pragma unroll
            for (int mi = 0; mi < 2; ++mi)
#pragma unroll
                for (int h = 0; h < 2; ++h) {
                    const int row = wrow * 32 + mi * 16 + g + h * 8;
                    part[row * 4 + wcol] = make_float2(s[mi][h], ss[mi][h]);
                }
        __syncthreads();

        const float* s_g = (const float*)(smem + GAM_OFF);
        const float* s_bb = (const float*)(smem + BET_OFF);
#pragma unroll
        for (int mi = 0; mi < 2; ++mi)
#pragma unroll
            for (int h = 0; h < 2; ++h) {
                const int row = wrow * 32 + mi * 16 + g + h * 8;
                if (row >= valid) continue;
                float2 p0 = part[row * 4], p1 = part[row * 4 + 1];
                float2 p2 = part[row * 4 + 2], p3 = part[row * 4 + 3];
                const float mu = (p0.x + p1.x + p2.x + p3.x) * (1.f / 128.f);
                const float var =
                    (p0.y + p1.y + p2.y + p3.y) * (1.f / 128.f) - mu * mu;
                const float inv = rsqrtf(var + LN_EPS);
                const size_t gro = (size_t)(base + row) * 128;
                const float* res = (EDGE ? ef : nf) + gro;
                float* op = out + gro;
                float* ap = nullptr;
                if (EDGE) {
                    const int rv = ((const int*)(smem + RIDX_OFF))[row];
                    ap = g_agg + (size_t)rv * 128;
                }
#pragma unroll
                for (int ni = 0; ni < 4; ++ni) {
                    const int col = wcol * 32 + ni * 8 + t4 * 2;
                    const float y0 = acc[mi][ni][h * 2];
                    const float y1 = acc[mi][ni][h * 2 + 1];
                    const float m0 = (y0 - mu) * inv * s_g[col] + s_bb[col];
                    const float m1 = (y1 - mu) * inv * s_g[col + 1] + s_bb[col + 1];
                    if (EDGE) red_add_v2(ap + col, m0, m1);
                    float2 r2 = *(const float2*)(res + col);
                    *(float2*)(op + col) = make_float2(m0 + r2.x, m1 + r2.y);
                }
            }
    }
}

// ---------------------------------------------------------------------------
extern "C" void kernel_launch(void* const* d_in, const int* in_sizes, int n_in,
                              void* d_out, int out_size) {
    const float* nf  = (const float*)d_in[0];
    const float* ef  = (const float*)d_in[1];
    const int*   snd = (const int*)d_in[2];
    const int*   rcv = (const int*)d_in[3];
    const float* We1 = (const float*)d_in[4];
    const float* be1 = (const float*)d_in[5];
    const float* We2 = (const float*)d_in[6];
    const float* be2 = (const float*)d_in[7];
    const float* ge  = (const float*)d_in[8];
    const float* bbe = (const float*)d_in[9];
    const float* Wn1 = (const float*)d_in[10];
    const float* bn1 = (const float*)d_in[11];
    const float* Wn2 = (const float*)d_in[12];
    const float* bn2 = (const float*)d_in[13];
    const float* gn  = (const float*)d_in[14];
    const float* bbn = (const float*)d_in[15];

    float* out_nodes = (float*)d_out;
    float* out_edges = out_nodes + (size_t)N_NODES * 128;

    cudaFuncSetAttribute(gnb_kernel<6, true>,
                         cudaFuncAttributeMaxDynamicSharedMemorySize, SMEM_TOTAL);
    cudaFuncSetAttribute(gnb_kernel<4, false>,
                         cudaFuncAttributeMaxDynamicSharedMemorySize, SMEM_TOTAL);

    prep_w<<<448, 256>>>(We1, We2, Wn1, Wn2);
    conv_nf_kernel<<<6250, 256>>>(nf);       // 50000*32 float4s
    zero_agg_kernel<<<6250, 256>>>();

    gnb_kernel<6, true><<<N_EDGES / 64, 256, SMEM_TOTAL>>>(
        nf, ef, snd, rcv, be1, be2, ge, bbe, out_edges);

    conv_agg_kernel<<<6250, 256>>>();

    gnb_kernel<4, false><<<(N_NODES + 63) / 64, 256, SMEM_TOTAL>>>(
        nf, nullptr, nullptr, nullptr, bn1, bn2, gn, bbn, out_nodes);
}